// round 8
// baseline (speedup 1.0000x reference)
#include <cuda_runtime.h>
#include <cuda_bf16.h>

// Problem constants
#define QN 256   // states
#define SN 128   // symbols
#define BN 1024  // batch
#define TN 128   // timesteps
#define MT 16    // batch rows per MMA tile
#define NTHREADS 512

// Device scratch (allocation-free rule: static __device__ globals)
__device__ unsigned g_Pbf[SN * QN * QN / 2];   // bf16x2 exp(A), [s][q][q'] : 16 MB
__device__ float    g_alpha[2][BN * QN];       // ping-pong linear alphas (scaled)
__device__ int      g_order[TN * BN];          // per-t batch indices grouped by symbol
__device__ int2     g_bkt[TN * SN];            // per (t,s): {start, cnt} in g_order
__device__ int      g_flag[BN];                // per-row alpha version (reset per run)

// Dynamic SMEM layout (bytes)
#define A_OFF   0
#define A_ROW   528                       // 256 bf16 + 16B pad (conflict-free ldmatrix)
#define P_OFF   (32 * A_ROW)              // A holds up to 32 rows: 16896
#define P_ROW   528
#define SB_OFF  (P_OFF + 256 * P_ROW)     // 16896 + 135168 = 152064
#define SH_BYTES (SB_OFF + 128)           // 152192 (dynamic, opt-in; 1 CTA/SM)

// ---------------------------------------------------------------------------
__device__ __forceinline__ unsigned f22bf(float lo, float hi) {
    unsigned r;
    asm("cvt.rn.bf16x2.f32 %0, %1, %2;" : "=r"(r) : "f"(hi), "f"(lo));  // a->hi, b->lo
    return r;
}
__device__ __forceinline__ void ldmA(unsigned a[4], unsigned addr) {
    asm volatile("ldmatrix.sync.aligned.m8n8.x4.shared.b16 {%0,%1,%2,%3}, [%4];"
                 : "=r"(a[0]), "=r"(a[1]), "=r"(a[2]), "=r"(a[3]) : "r"(addr));
}
__device__ __forceinline__ void ldmBT(unsigned b[4], unsigned addr) {
    asm volatile("ldmatrix.sync.aligned.m8n8.x4.trans.shared.b16 {%0,%1,%2,%3}, [%4];"
                 : "=r"(b[0]), "=r"(b[1]), "=r"(b[2]), "=r"(b[3]) : "r"(addr));
}
__device__ __forceinline__ void mma16816(float d[4], const unsigned a[4],
                                         unsigned b0, unsigned b1) {
    asm volatile("mma.sync.aligned.m16n8k16.row.col.f32.bf16.bf16.f32 "
                 "{%0,%1,%2,%3},{%4,%5,%6,%7},{%8,%9},{%0,%1,%2,%3};"
                 : "+f"(d[0]), "+f"(d[1]), "+f"(d[2]), "+f"(d[3])
                 : "r"(a[0]), "r"(a[1]), "r"(a[2]), "r"(a[3]), "r"(b0), "r"(b1));
}
__device__ __forceinline__ void cpasync16(unsigned saddr, const void* g) {
    asm volatile("cp.async.cg.shared.global [%0], [%1], 16;" :: "r"(saddr), "l"(g));
}
__device__ __forceinline__ void wait_flag(const int* f, int tgt) {
    int v;
    do {
        asm volatile("ld.acquire.gpu.global.s32 %0, [%1];" : "=r"(v) : "l"(f));
    } while (v < tgt);
}
__device__ __forceinline__ void set_flag(int* f, int v) {
    asm volatile("st.release.gpu.global.s32 [%0], %1;" :: "l"(f), "r"(v) : "memory");
}

// ---------------------------------------------------------------------------
// P_bf16[s][q][q'] = bf16(exp(A[q][s][q'])), packed as bf16x2 (q' pairs)
__global__ void exp_kernel(const float* __restrict__ A) {
    int i = blockIdx.x * 256 + threadIdx.x;   // one thread per q'-pair
    int j2 = i & 127;
    int q = (i >> 7) & 255;
    int s = i >> 15;
    float2 v = *(const float2*)(A + (q << 15) + (s << 8) + 2 * j2);
    g_Pbf[(s << 15) + (q << 7) + j2] = f22bf(__expf(v.x), __expf(v.y));
}

// ---------------------------------------------------------------------------
// alpha_0 in buffer 0; per-row version flags reset to 0 every run.
__global__ void init_kernel(const float* __restrict__ init) {
    int b = blockIdx.x;
    int q = threadIdx.x;
    float iv = init[q];
    g_alpha[0][b * QN + q] = (iv > 0.0f) ? iv : 0.0f;
    if (q == 0) g_flag[b] = 0;
}

// ---------------------------------------------------------------------------
// Per-timestep bucketing: group batch indices by symbol; emit {start,cnt}.
__global__ void bucket_kernel(const int* __restrict__ xs) {
    int t = blockIdx.x;
    int tid = threadIdx.x;
    __shared__ int cnt[SN];
    __shared__ int seg[SN];
    __shared__ int off[SN];
    if (tid < SN) cnt[tid] = 0;
    __syncthreads();
    for (int b = tid; b < BN; b += 256)
        atomicAdd(&cnt[xs[b * TN + t]], 1);
    __syncthreads();
    if (tid == 0) {
        int acc = 0;
        for (int s = 0; s < SN; s++) { seg[s] = acc; off[s] = acc; acc += cnt[s]; }
    }
    __syncthreads();
    for (int b = tid; b < BN; b += 256) {
        int s = xs[b * TN + t];
        int pos = atomicAdd(&off[s], 1);
        g_order[t * BN + pos] = b;
    }
    __syncthreads();
    if (tid < SN)
        g_bkt[t * SN + tid] = make_int2(seg[tid], cnt[tid]);
}

// ---------------------------------------------------------------------------
// Persistent dataflow FSA kernel: one CTA per symbol, P[s] SMEM-resident.
// No grid barrier: per-row monotonic version flags. Consumer spins (acquire)
// until flag[b] >= t before reading alpha_t[b]; producer releases flag[b]=t+1
// after the row's stores. Ping-pong WAR is safe because flag[b] >= t+1
// certifies the step-t+1 reader already consumed buffer[t&1] row b.
__global__ void __launch_bounds__(NTHREADS, 1) fsa_kernel() {
    extern __shared__ __align__(16) unsigned char sh[];
    unsigned shb = (unsigned)__cvta_generic_to_shared(sh);
    const int s = blockIdx.x;
    const int tid = threadIdx.x, w = tid >> 5, lane = tid & 31;
    int* sb = (int*)(sh + SB_OFF);

    // ---- load P[s] (256 rows x 512B) into SMEM once
    {
        const char* gP = (const char*)g_Pbf + ((size_t)s << 17);
        for (int i = tid; i < 256 * 32; i += NTHREADS) {
            int r = i >> 5, c = i & 31;
            cpasync16(shb + P_OFF + r * P_ROW + c * 16, gP + (size_t)r * 512 + c * 16);
        }
        asm volatile("cp.async.commit_group;");
        asm volatile("cp.async.wait_group 0;");
        __syncthreads();
    }

    const float sc = 0.00390625f;   // 2^-8 exact per-step renorm

    for (int t = 0; t < TN; t++) {
        const float* __restrict__ pin  = g_alpha[t & 1];
        float*       __restrict__ pout = g_alpha[(t & 1) ^ 1];
        const int2 bkt = g_bkt[t * SN + s];
        const int start = bkt.x, cnt = bkt.y;

        int o = 0;
        while (o < cnt) {
            const int rem = cnt - o;
            if (rem > MT) {
                // ============ two-tile mode (up to 32 rows, warp-split) ====
                const int m = min(rem, 32);
                {   // stage: row = tid>>4 (2 rows/warp), 16 floats/thread
                    int row = tid >> 4, seg = tid & 15;
                    int b = 0;
                    if (row < m) {
                        b = g_order[t * BN + start + o + row];
                        if ((tid & 15) == 0) wait_flag(&g_flag[b], t);
                    }
                    __syncwarp();
                    uint4 pk0 = make_uint4(0,0,0,0), pk1 = make_uint4(0,0,0,0);
                    if (row < m) {
                        const float* p = pin + b * QN + seg * 16;
                        float4 x0 = __ldcg((const float4*)p);
                        float4 x1 = __ldcg((const float4*)(p + 4));
                        float4 x2 = __ldcg((const float4*)(p + 8));
                        float4 x3 = __ldcg((const float4*)(p + 12));
                        pk0.x = f22bf(x0.x*sc, x0.y*sc); pk0.y = f22bf(x0.z*sc, x0.w*sc);
                        pk0.z = f22bf(x1.x*sc, x1.y*sc); pk0.w = f22bf(x1.z*sc, x1.w*sc);
                        pk1.x = f22bf(x2.x*sc, x2.y*sc); pk1.y = f22bf(x2.z*sc, x2.w*sc);
                        pk1.z = f22bf(x3.x*sc, x3.y*sc); pk1.w = f22bf(x3.z*sc, x3.w*sc);
                    }
                    *(uint4*)(sh + A_OFF + row * A_ROW + seg * 32) = pk0;
                    *(uint4*)(sh + A_OFF + row * A_ROW + seg * 32 + 16) = pk1;
                    if (tid < 32)
                        sb[tid] = (tid < m) ? g_order[t * BN + start + o + tid] : 0;
                }
                __syncthreads();

                const int g = w >> 3, wg = w & 7;       // tile group, warp-in-group
                const int mg = min(m - g * MT, MT);     // rows in this tile
                float d[4][4];
                #pragma unroll
                for (int j = 0; j < 4; j++)
                    #pragma unroll
                    for (int r = 0; r < 4; r++) d[j][r] = 0.0f;

                const unsigned aA = shb + A_OFF + (g * MT + (lane & 15)) * A_ROW
                                    + (lane >> 4) * 16;
                const unsigned aB = shb + P_OFF + (lane & 15) * P_ROW
                                    + (wg * 32 + (lane >> 4) * 8) * 2;
                #pragma unroll
                for (int k16 = 0; k16 < 16; k16++) {
                    unsigned a[4], b[8];
                    ldmA(a, aA + k16 * 32);
                    unsigned baddr = aB + k16 * 16 * P_ROW;
                    ldmBT(b + 0, baddr);
                    ldmBT(b + 4, baddr + 32);
                    mma16816(d[0], a, b[0], b[1]);
                    mma16816(d[1], a, b[2], b[3]);
                    mma16816(d[2], a, b[4], b[5]);
                    mma16816(d[3], a, b[6], b[7]);
                }
                int m0 = lane >> 2;
                int q0 = wg * 32 + 2 * (lane & 3);
                #pragma unroll
                for (int j = 0; j < 4; j++) {
                    int n = q0 + j * 8;
                    if (m0 < mg)
                        *(float2*)(pout + sb[g*MT + m0] * QN + n)
                            = make_float2(d[j][0], d[j][1]);
                    if (m0 + 8 < mg)
                        *(float2*)(pout + sb[g*MT + m0 + 8] * QN + n)
                            = make_float2(d[j][2], d[j][3]);
                }
                __syncthreads();                 // all stores of this tile done
                if (tid < m) set_flag(&g_flag[sb[tid]], t + 1);
                __syncthreads();                 // protect sb/A before restage
                o += 32;
            } else {
                // ============ single-tile mode (<=16 rows, 16 warps) =======
                const int m = rem;
                {   // stage: row = tid>>5 (warp per row), 8 floats/thread
                    int row = tid >> 5, seg = tid & 31;
                    int b = 0;
                    if (row < m) {
                        b = g_order[t * BN + start + o + row];
                        if (lane == 0) wait_flag(&g_flag[b], t);
                    }
                    __syncwarp();
                    uint4 pk = make_uint4(0,0,0,0);
                    if (row < m) {
                        const float* p = pin + b * QN + seg * 8;
                        float4 x0 = __ldcg((const float4*)p);
                        float4 x1 = __ldcg((const float4*)(p + 4));
                        pk.x = f22bf(x0.x*sc, x0.y*sc); pk.y = f22bf(x0.z*sc, x0.w*sc);
                        pk.z = f22bf(x1.x*sc, x1.y*sc); pk.w = f22bf(x1.z*sc, x1.w*sc);
                    }
                    *(uint4*)(sh + A_OFF + row * A_ROW + seg * 16) = pk;
                    if (tid < MT)
                        sb[tid] = (tid < m) ? g_order[t * BN + start + o + tid] : 0;
                }
                __syncthreads();

                float d[2][4];
                #pragma unroll
                for (int j = 0; j < 2; j++)
                    #pragma unroll
                    for (int r = 0; r < 4; r++) d[j][r] = 0.0f;

                const unsigned aA = shb + A_OFF + (lane & 15) * A_ROW
                                    + (lane >> 4) * 16;
                const unsigned aB = shb + P_OFF + (lane & 15) * P_ROW
                                    + (w * 16 + (lane >> 4) * 8) * 2;
                #pragma unroll
                for (int k16 = 0; k16 < 16; k16++) {
                    unsigned a[4], b[4];
                    ldmA(a, aA + k16 * 32);
                    ldmBT(b, aB + k16 * 16 * P_ROW);   // n-tiles w*16, w*16+8
                    mma16816(d[0], a, b[0], b[1]);
                    mma16816(d[1], a, b[2], b[3]);
                }
                int m0 = lane >> 2;
                int q0 = w * 16 + 2 * (lane & 3);
                #pragma unroll
                for (int j = 0; j < 2; j++) {
                    int n = q0 + j * 8;
                    if (m0 < m)
                        *(float2*)(pout + sb[m0] * QN + n)
                            = make_float2(d[j][0], d[j][1]);
                    if (m0 + 8 < m)
                        *(float2*)(pout + sb[m0 + 8] * QN + n)
                            = make_float2(d[j][2], d[j][3]);
                }
                __syncthreads();                 // all stores of this tile done
                if (tid < m) set_flag(&g_flag[sb[tid]], t + 1);
                __syncthreads();                 // protect sb/A before restage
                o += MT;
            }
        }
    }
}

// ---------------------------------------------------------------------------
// out[b] = log( sum_q alpha_lin[b][q] * exp(final[q]) ) + 128*ln(256)
__global__ void final_kernel(const float* __restrict__ finalw, float* __restrict__ out) {
    int b = blockIdx.x * 8 + (threadIdx.x >> 5);
    int lane = threadIdx.x & 31;
    const float* ar = g_alpha[0] + b * QN;   // T=128 even -> buffer 0
    float sum = 0.0f;
    #pragma unroll
    for (int i = 0; i < 8; i++) {
        int q = lane + 32 * i;
        sum += ar[q] * __expf(finalw[q]);
    }
    #pragma unroll
    for (int o = 16; o > 0; o >>= 1) sum += __shfl_xor_sync(0xFFFFFFFFu, sum, o);
    if (lane == 0)
        out[b] = logf(sum) + (float)(128.0 * 5.545177444479562);  // T * ln(256)
}

// ---------------------------------------------------------------------------
extern "C" void kernel_launch(void* const* d_in, const int* in_sizes, int n_in,
                              void* d_out, int out_size) {
    const float* A      = (const float*)d_in[0];  // [Q,S,Q] fp32
    const float* init   = (const float*)d_in[1];  // [Q]
    const float* finalw = (const float*)d_in[2];  // [Q]
    const int*   xs     = (const int*)d_in[3];    // [B,T] int32
    float* out = (float*)d_out;                   // [B]

    cudaFuncSetAttribute(fsa_kernel,
                         cudaFuncAttributeMaxDynamicSharedMemorySize, SH_BYTES);

    exp_kernel<<<(SN * QN * QN / 2) / 256, 256>>>(A);
    init_kernel<<<BN, QN>>>(init);
    bucket_kernel<<<TN, 256>>>(xs);
    fsa_kernel<<<SN, NTHREADS, SH_BYTES>>>();
    final_kernel<<<BN / 8, 256>>>(finalw, out);
}

// round 10
// speedup vs baseline: 1.1222x; 1.1222x over previous
#include <cuda_runtime.h>
#include <cuda_bf16.h>

// Problem constants
#define QN 256   // states
#define SN 128   // symbols
#define BN 1024  // batch
#define TN 128   // timesteps
#define MT 16    // batch rows per MMA tile
#define NTHREADS 512

// Device scratch (allocation-free rule: static __device__ globals)
__device__ unsigned g_Pbf[SN * QN * QN / 2];     // bf16x2 exp(A), [s][q][q'] : 16 MB
__device__ uint4    g_alpha[2][BN * QN / 8];     // ping-pong bf16 alphas (512B/row)
__device__ int      g_order[TN * BN];            // per-t batch indices grouped by symbol
__device__ int2     g_bkt[TN * SN];              // per (t,s): {start, cnt}
__device__ unsigned g_bar;                       // grid barrier counter (reset per run)

// Dynamic SMEM layout (bytes)
#define A_OFF   0
#define A_ROW   528                       // 256 bf16 (512B) + 16B pad
#define P_OFF   (32 * A_ROW)              // 16896
#define P_ROW   528
#define SB_OFF  (P_OFF + 256 * P_ROW)     // 152064
#define SH_BYTES (SB_OFF + 128)           // 152192 (dynamic, opt-in; 1 CTA/SM)

// ---------------------------------------------------------------------------
__device__ __forceinline__ unsigned f22bf(float lo, float hi) {
    unsigned r;
    asm("cvt.rn.bf16x2.f32 %0, %1, %2;" : "=r"(r) : "f"(hi), "f"(lo));  // {hi,lo}
    return r;
}
__device__ __forceinline__ void ldmA(unsigned a[4], unsigned addr) {
    asm volatile("ldmatrix.sync.aligned.m8n8.x4.shared.b16 {%0,%1,%2,%3}, [%4];"
                 : "=r"(a[0]), "=r"(a[1]), "=r"(a[2]), "=r"(a[3]) : "r"(addr));
}
__device__ __forceinline__ void ldmBT(unsigned b[4], unsigned addr) {
    asm volatile("ldmatrix.sync.aligned.m8n8.x4.trans.shared.b16 {%0,%1,%2,%3}, [%4];"
                 : "=r"(b[0]), "=r"(b[1]), "=r"(b[2]), "=r"(b[3]) : "r"(addr));
}
// Non-trans x2: for B operand whose SOURCE is stored n-major (rows = n, cols = k).
// Row-major n x k == col-major k x n, so the B fragment needs NO transpose.
__device__ __forceinline__ void ldmN2(unsigned b[2], unsigned addr) {
    asm volatile("ldmatrix.sync.aligned.m8n8.x2.shared.b16 {%0,%1}, [%2];"
                 : "=r"(b[0]), "=r"(b[1]) : "r"(addr));
}
__device__ __forceinline__ void mma16816(float d[4], const unsigned a[4],
                                         unsigned b0, unsigned b1) {
    asm volatile("mma.sync.aligned.m16n8k16.row.col.f32.bf16.bf16.f32 "
                 "{%0,%1,%2,%3},{%4,%5,%6,%7},{%8,%9},{%0,%1,%2,%3};"
                 : "+f"(d[0]), "+f"(d[1]), "+f"(d[2]), "+f"(d[3])
                 : "r"(a[0]), "r"(a[1]), "r"(a[2]), "r"(a[3]), "r"(b0), "r"(b1));
}
__device__ __forceinline__ void cpasync16(unsigned saddr, const void* g) {
    asm volatile("cp.async.cg.shared.global [%0], [%1], 16;" :: "r"(saddr), "l"(g));
}

// ---------------------------------------------------------------------------
// P_bf16[s][q][q'] = bf16(exp(A[q][s][q'])), packed as bf16x2 (q' pairs)
__global__ void exp_kernel(const float* __restrict__ A) {
    int i = blockIdx.x * 256 + threadIdx.x;   // one thread per q'-pair
    int j2 = i & 127;
    int q = (i >> 7) & 255;
    int s = i >> 15;
    float2 v = *(const float2*)(A + (q << 15) + (s << 8) + 2 * j2);
    g_Pbf[(s << 15) + (q << 7) + j2] = f22bf(__expf(v.x), __expf(v.y));
}

// ---------------------------------------------------------------------------
// alpha_0 (bf16, linear space) in buffer 0.
__global__ void init_kernel(const float* __restrict__ init) {
    int b = blockIdx.x;
    int q = threadIdx.x;
    float iv = init[q];
    ((__nv_bfloat16*)g_alpha[0])[b * QN + q] =
        __float2bfloat16((iv > 0.0f) ? iv : 0.0f);
}

// ---------------------------------------------------------------------------
// Per-timestep bucketing; resets the grid barrier counter (stream-ordered).
__global__ void bucket_kernel(const int* __restrict__ xs) {
    int t = blockIdx.x;
    int tid = threadIdx.x;
    if (t == 0 && tid == 0) g_bar = 0u;
    __shared__ int cnt[SN];
    __shared__ int seg[SN];
    __shared__ int off[SN];
    if (tid < SN) cnt[tid] = 0;
    __syncthreads();
    for (int b = tid; b < BN; b += 256)
        atomicAdd(&cnt[xs[b * TN + t]], 1);
    __syncthreads();
    if (tid == 0) {
        int acc = 0;
        for (int s = 0; s < SN; s++) { seg[s] = acc; off[s] = acc; acc += cnt[s]; }
    }
    __syncthreads();
    for (int b = tid; b < BN; b += 256) {
        int s = xs[b * TN + t];
        int pos = atomicAdd(&off[s], 1);
        g_order[t * BN + pos] = b;
    }
    __syncthreads();
    if (tid < SN)
        g_bkt[t * SN + tid] = make_int2(seg[tid], cnt[tid]);
}

// ---------------------------------------------------------------------------
// Persistent FSA kernel: one CTA per symbol, P[s] SMEM-resident for all steps.
// bf16 alpha handoff (scale applied at epilogue; staging is pure copy).
// Modes: cnt<=8 transposed GEMM (D^T = P^T x alpha: half the MMAs; A-operand
// = P via x4.trans, B-operand = alpha via x2 NON-trans since alpha rows = n);
// 9..16 single-tile; 17+ two-tile. Global barrier per step.
__global__ void __launch_bounds__(NTHREADS, 1) fsa_kernel() {
    extern __shared__ __align__(16) unsigned char sh[];
    unsigned shb = (unsigned)__cvta_generic_to_shared(sh);
    const int s = blockIdx.x;
    const int tid = threadIdx.x, w = tid >> 5, lane = tid & 31;
    int* sb = (int*)(sh + SB_OFF);

    // ---- load P[s] (256 rows x 512B) into SMEM once
    {
        const char* gP = (const char*)g_Pbf + ((size_t)s << 17);
        for (int i = tid; i < 256 * 32; i += NTHREADS) {
            int r = i >> 5, c = i & 31;
            cpasync16(shb + P_OFF + r * P_ROW + c * 16, gP + (size_t)r * 512 + c * 16);
        }
        asm volatile("cp.async.commit_group;");
        asm volatile("cp.async.wait_group 0;");
        __syncthreads();
    }

    const float sc = 0.00390625f;   // 2^-8 exact per-step renorm (at epilogue)

    for (int t = 0; t < TN; t++) {
        const __nv_bfloat16* __restrict__ pin = (const __nv_bfloat16*)g_alpha[t & 1];
        __nv_bfloat16* __restrict__ pout = (__nv_bfloat16*)g_alpha[(t & 1) ^ 1];
        const int2 bkt = g_bkt[t * SN + s];
        const int start = bkt.x, cnt = bkt.y;

        int o = 0;
        while (o < cnt) {
            const int rem = cnt - o;
            if (rem <= 8) {
                // ========= transposed mode (<=8 rows): D^T = P^T x alpha ====
                const int m = rem;
                if (w < 8) {   // warp w stages alpha row w (zero-padded)
                    uint4 pk = make_uint4(0, 0, 0, 0);
                    if (w < m) {
                        int b = g_order[t * BN + start + o + w];
                        pk = __ldcg((const uint4*)(pin + b * QN) + lane);
                    }
                    *(uint4*)(sh + A_OFF + w * A_ROW + lane * 16) = pk;
                }
                if (tid < 8)
                    sb[tid] = (tid < m) ? g_order[t * BN + start + o + tid] : 0;
                __syncthreads();

                float d[4] = {0.0f, 0.0f, 0.0f, 0.0f};
                // A-frag = P^T tile: x4.trans on P rows k, cols q'=w*16(+8)
                const unsigned aP = shb + P_OFF
                    + ((lane & 7) + ((lane >> 4) & 1) * 8) * P_ROW
                    + (w * 16 + ((lane >> 3) & 1) * 8) * 2;
                // B-frag = alpha (rows n=m, cols k): NON-trans x2,
                // tile0 = (n0-7, k0-7), tile1 = (n0-7, k8-15)
                const unsigned aAl = shb + A_OFF + (lane & 7) * A_ROW
                    + ((lane >> 3) & 1) * 16;
                #pragma unroll
                for (int k16 = 0; k16 < 16; k16++) {
                    unsigned a[4], b[2];
                    ldmBT(a, aP + k16 * 16 * P_ROW);
                    ldmN2(b, aAl + k16 * 32);
                    mma16816(d, a, b[0], b[1]);
                }

                // D^T frag: q' = w*16 + lane>>2 (+8), b-slot n = 2*(lane&3)(+1)
                int n = 2 * (lane & 3);
                int qp = w * 16 + (lane >> 2);
                if (n < m) {
                    __nv_bfloat16* r0 = pout + sb[n] * QN + qp;
                    r0[0] = __float2bfloat16(d[0] * sc);
                    r0[8] = __float2bfloat16(d[2] * sc);
                }
                if (n + 1 < m) {
                    __nv_bfloat16* r1 = pout + sb[n + 1] * QN + qp;
                    r1[0] = __float2bfloat16(d[1] * sc);
                    r1[8] = __float2bfloat16(d[3] * sc);
                }
                __syncthreads();
                o += 8;
            } else if (rem <= MT) {
                // ========= single-tile mode (9..16 rows, 16 warps) ==========
                const int m = rem;
                {   // warp w stages alpha row w (zero-padded)
                    uint4 pk = make_uint4(0, 0, 0, 0);
                    if (w < m) {
                        int b = g_order[t * BN + start + o + w];
                        pk = __ldcg((const uint4*)(pin + b * QN) + lane);
                    }
                    *(uint4*)(sh + A_OFF + w * A_ROW + lane * 16) = pk;
                    if (tid < MT)
                        sb[tid] = (tid < m) ? g_order[t * BN + start + o + tid] : 0;
                }
                __syncthreads();

                float d[2][4];
                #pragma unroll
                for (int j = 0; j < 2; j++)
                    #pragma unroll
                    for (int r = 0; r < 4; r++) d[j][r] = 0.0f;

                const unsigned aA = shb + A_OFF + (lane & 15) * A_ROW
                                    + (lane >> 4) * 16;
                const unsigned aB = shb + P_OFF + (lane & 15) * P_ROW
                                    + (w * 16 + (lane >> 4) * 8) * 2;
                #pragma unroll
                for (int k16 = 0; k16 < 16; k16++) {
                    unsigned a[4], b[4];
                    ldmA(a, aA + k16 * 32);
                    ldmBT(b, aB + k16 * 16 * P_ROW);
                    mma16816(d[0], a, b[0], b[1]);
                    mma16816(d[1], a, b[2], b[3]);
                }
                unsigned* pu = (unsigned*)pout;
                int m0 = lane >> 2;
                int q0 = w * 16 + 2 * (lane & 3);
                #pragma unroll
                for (int j = 0; j < 2; j++) {
                    int n = q0 + j * 8;
                    if (m0 < m)
                        pu[sb[m0] * (QN / 2) + (n >> 1)] =
                            f22bf(d[j][0] * sc, d[j][1] * sc);
                    if (m0 + 8 < m)
                        pu[sb[m0 + 8] * (QN / 2) + (n >> 1)] =
                            f22bf(d[j][2] * sc, d[j][3] * sc);
                }
                __syncthreads();
                o += MT;
            } else {
                // ========= two-tile mode (17..32 rows, warp-split) ==========
                const int m = min(rem, 32);
                {   // half-warp per row: row = tid>>4, 32B per thread
                    int row = tid >> 4, seg = tid & 15;
                    uint4 p0 = make_uint4(0,0,0,0), p1 = make_uint4(0,0,0,0);
                    if (row < m) {
                        int b = g_order[t * BN + start + o + row];
                        const uint4* p = (const uint4*)(pin + b * QN) + seg * 2;
                        p0 = __ldcg(p);
                        p1 = __ldcg(p + 1);
                    }
                    *(uint4*)(sh + A_OFF + row * A_ROW + seg * 32) = p0;
                    *(uint4*)(sh + A_OFF + row * A_ROW + seg * 32 + 16) = p1;
                    if (tid < 32)
                        sb[tid] = (tid < m) ? g_order[t * BN + start + o + tid] : 0;
                }
                __syncthreads();

                const int g = w >> 3, wg = w & 7;
                const int mg = min(m - g * MT, MT);
                float d[4][4];
                #pragma unroll
                for (int j = 0; j < 4; j++)
                    #pragma unroll
                    for (int r = 0; r < 4; r++) d[j][r] = 0.0f;

                const unsigned aA = shb + A_OFF + (g * MT + (lane & 15)) * A_ROW
                                    + (lane >> 4) * 16;
                const unsigned aB = shb + P_OFF + (lane & 15) * P_ROW
                                    + (wg * 32 + (lane >> 4) * 8) * 2;
                #pragma unroll
                for (int k16 = 0; k16 < 16; k16++) {
                    unsigned a[4], b[8];
                    ldmA(a, aA + k16 * 32);
                    unsigned baddr = aB + k16 * 16 * P_ROW;
                    ldmBT(b + 0, baddr);
                    ldmBT(b + 4, baddr + 32);
                    mma16816(d[0], a, b[0], b[1]);
                    mma16816(d[1], a, b[2], b[3]);
                    mma16816(d[2], a, b[4], b[5]);
                    mma16816(d[3], a, b[6], b[7]);
                }
                unsigned* pu = (unsigned*)pout;
                int m0 = lane >> 2;
                int q0 = wg * 32 + 2 * (lane & 3);
                #pragma unroll
                for (int j = 0; j < 4; j++) {
                    int n = q0 + j * 8;
                    if (m0 < mg)
                        pu[sb[g*MT + m0] * (QN / 2) + (n >> 1)] =
                            f22bf(d[j][0] * sc, d[j][1] * sc);
                    if (m0 + 8 < mg)
                        pu[sb[g*MT + m0 + 8] * (QN / 2) + (n >> 1)] =
                            f22bf(d[j][2] * sc, d[j][3] * sc);
                }
                __syncthreads();
                o += 32;
            }
        }

        // ---- grid barrier: release-add, acquire-poll, monotonic target
        if (tid == 0) {
            asm volatile("red.release.gpu.global.add.u32 [%0], 1;"
                         :: "l"(&g_bar) : "memory");
            const unsigned target = (unsigned)(t + 1) * (unsigned)SN;
            unsigned v;
            do {
                asm volatile("ld.acquire.gpu.u32 %0, [%1];" : "=r"(v) : "l"(&g_bar));
            } while (v < target);
        }
        __syncthreads();
    }
}

// ---------------------------------------------------------------------------
// out[b] = log( sum_q alpha_bf16[b][q] * exp(final[q]) ) + 128*ln(256)
__global__ void final_kernel(const float* __restrict__ finalw, float* __restrict__ out) {
    int b = blockIdx.x * 8 + (threadIdx.x >> 5);
    int lane = threadIdx.x & 31;
    const __nv_bfloat16* ar = (const __nv_bfloat16*)g_alpha[0] + b * QN;  // T even
    float sum = 0.0f;
    #pragma unroll
    for (int i = 0; i < 8; i++) {
        int q = lane + 32 * i;
        sum += __bfloat162float(ar[q]) * __expf(finalw[q]);
    }
    #pragma unroll
    for (int o = 16; o > 0; o >>= 1) sum += __shfl_xor_sync(0xFFFFFFFFu, sum, o);
    if (lane == 0)
        out[b] = logf(sum) + (float)(128.0 * 5.545177444479562);  // T * ln(256)
}

// ---------------------------------------------------------------------------
extern "C" void kernel_launch(void* const* d_in, const int* in_sizes, int n_in,
                              void* d_out, int out_size) {
    const float* A      = (const float*)d_in[0];  // [Q,S,Q] fp32
    const float* init   = (const float*)d_in[1];  // [Q]
    const float* finalw = (const float*)d_in[2];  // [Q]
    const int*   xs     = (const int*)d_in[3];    // [B,T] int32
    float* out = (float*)d_out;                   // [B]

    cudaFuncSetAttribute(fsa_kernel,
                         cudaFuncAttributeMaxDynamicSharedMemorySize, SH_BYTES);

    exp_kernel<<<(SN * QN * QN / 2) / 256, 256>>>(A);
    init_kernel<<<BN, QN>>>(init);
    bucket_kernel<<<TN, 256>>>(xs);
    fsa_kernel<<<SN, NTHREADS, SH_BYTES>>>();
    final_kernel<<<BN / 8, 256>>>(finalw, out);
}

// round 11
// speedup vs baseline: 1.1372x; 1.0134x over previous
#include <cuda_runtime.h>
#include <cuda_bf16.h>

// Problem constants
#define QN 256   // states
#define SN 128   // symbols
#define BN 1024  // batch
#define TN 128   // timesteps
#define MT 16    // batch rows per MMA tile
#define NTHREADS 512

// Device scratch (allocation-free rule: static __device__ globals)
__device__ unsigned g_Pbf[SN * QN * QN / 2];     // bf16x2 exp(A), [s][q][q'] : 16 MB
__device__ uint4    g_alpha[2][BN * QN / 8];     // ping-pong bf16 alphas (512B/row)
__device__ int      g_order[TN * BN];            // per-t batch indices grouped by symbol
__device__ int2     g_bkt[TN * SN];              // per (t,s): {start, cnt}
__device__ unsigned g_bar;                       // grid barrier counter (reset per run)

// Dynamic SMEM layout (bytes)
#define A_OFF   0
#define A_ROW   528                       // 256 bf16 (512B) + 16B pad
#define P_OFF   (32 * A_ROW)              // 16896
#define P_ROW   528
#define SB_OFF  (P_OFF + 256 * P_ROW)     // 152064 ; prefetched bucket row list
#define SH_BYTES (SB_OFF + 4096)          // 156160 (sb: up to 1024 ints)

// ---------------------------------------------------------------------------
__device__ __forceinline__ unsigned f22bf(float lo, float hi) {
    unsigned r;
    asm("cvt.rn.bf16x2.f32 %0, %1, %2;" : "=r"(r) : "f"(hi), "f"(lo));  // {hi,lo}
    return r;
}
__device__ __forceinline__ void ldmA(unsigned a[4], unsigned addr) {
    asm volatile("ldmatrix.sync.aligned.m8n8.x4.shared.b16 {%0,%1,%2,%3}, [%4];"
                 : "=r"(a[0]), "=r"(a[1]), "=r"(a[2]), "=r"(a[3]) : "r"(addr));
}
__device__ __forceinline__ void ldmBT(unsigned b[4], unsigned addr) {
    asm volatile("ldmatrix.sync.aligned.m8n8.x4.trans.shared.b16 {%0,%1,%2,%3}, [%4];"
                 : "=r"(b[0]), "=r"(b[1]), "=r"(b[2]), "=r"(b[3]) : "r"(addr));
}
// Non-trans x2: for B operand whose SOURCE is stored n-major (rows = n, cols = k).
__device__ __forceinline__ void ldmN2(unsigned b[2], unsigned addr) {
    asm volatile("ldmatrix.sync.aligned.m8n8.x2.shared.b16 {%0,%1}, [%2];"
                 : "=r"(b[0]), "=r"(b[1]) : "r"(addr));
}
__device__ __forceinline__ void mma16816(float d[4], const unsigned a[4],
                                         unsigned b0, unsigned b1) {
    asm volatile("mma.sync.aligned.m16n8k16.row.col.f32.bf16.bf16.f32 "
                 "{%0,%1,%2,%3},{%4,%5,%6,%7},{%8,%9},{%0,%1,%2,%3};"
                 : "+f"(d[0]), "+f"(d[1]), "+f"(d[2]), "+f"(d[3])
                 : "r"(a[0]), "r"(a[1]), "r"(a[2]), "r"(a[3]), "r"(b0), "r"(b1));
}
__device__ __forceinline__ void cpasync16(unsigned saddr, const void* g) {
    asm volatile("cp.async.cg.shared.global [%0], [%1], 16;" :: "r"(saddr), "l"(g));
}

// ---------------------------------------------------------------------------
// P_bf16[s][q][q'] = bf16(exp(A[q][s][q'])), packed as bf16x2 (q' pairs)
__global__ void exp_kernel(const float* __restrict__ A) {
    int i = blockIdx.x * 256 + threadIdx.x;   // one thread per q'-pair
    int j2 = i & 127;
    int q = (i >> 7) & 255;
    int s = i >> 15;
    float2 v = *(const float2*)(A + (q << 15) + (s << 8) + 2 * j2);
    g_Pbf[(s << 15) + (q << 7) + j2] = f22bf(__expf(v.x), __expf(v.y));
}

// ---------------------------------------------------------------------------
// alpha_0 (bf16, linear space) in buffer 0.
__global__ void init_kernel(const float* __restrict__ init) {
    int b = blockIdx.x;
    int q = threadIdx.x;
    float iv = init[q];
    ((__nv_bfloat16*)g_alpha[0])[b * QN + q] =
        __float2bfloat16((iv > 0.0f) ? iv : 0.0f);
}

// ---------------------------------------------------------------------------
// Per-timestep bucketing; resets the grid barrier counter (stream-ordered).
__global__ void bucket_kernel(const int* __restrict__ xs) {
    int t = blockIdx.x;
    int tid = threadIdx.x;
    if (t == 0 && tid == 0) g_bar = 0u;
    __shared__ int cnt[SN];
    __shared__ int seg[SN];
    __shared__ int off[SN];
    if (tid < SN) cnt[tid] = 0;
    __syncthreads();
    for (int b = tid; b < BN; b += 256)
        atomicAdd(&cnt[xs[b * TN + t]], 1);
    __syncthreads();
    if (tid == 0) {
        int acc = 0;
        for (int s = 0; s < SN; s++) { seg[s] = acc; off[s] = acc; acc += cnt[s]; }
    }
    __syncthreads();
    for (int b = tid; b < BN; b += 256) {
        int s = xs[b * TN + t];
        int pos = atomicAdd(&off[s], 1);
        g_order[t * BN + pos] = b;
    }
    __syncthreads();
    if (tid < SN)
        g_bkt[t * SN + tid] = make_int2(seg[tid], cnt[tid]);
}

// ---------------------------------------------------------------------------
// Persistent FSA kernel: one CTA per symbol, P[s] SMEM-resident for all steps.
// Step-constant metadata (bucket bounds + row index list) is prefetched into
// SMEM BEFORE each barrier so the post-barrier critical path starts directly
// with the alpha loads. Dual accumulators halve the MMA dependency chain.
// Modes: cnt<=8 transposed GEMM; 9..16 single-tile; 17+ two-tile.
__global__ void __launch_bounds__(NTHREADS, 1) fsa_kernel() {
    extern __shared__ __align__(16) unsigned char sh[];
    unsigned shb = (unsigned)__cvta_generic_to_shared(sh);
    const int s = blockIdx.x;
    const int tid = threadIdx.x, w = tid >> 5, lane = tid & 31;
    int* sb = (int*)(sh + SB_OFF);

    // ---- load P[s] (256 rows x 512B) into SMEM once
    {
        const char* gP = (const char*)g_Pbf + ((size_t)s << 17);
        for (int i = tid; i < 256 * 32; i += NTHREADS) {
            int r = i >> 5, c = i & 31;
            cpasync16(shb + P_OFF + r * P_ROW + c * 16, gP + (size_t)r * 512 + c * 16);
        }
        asm volatile("cp.async.commit_group;");
        asm volatile("cp.async.wait_group 0;");
    }

    const float sc = 0.00390625f;   // 2^-8 exact per-step renorm (at epilogue)

    // ---- prefetch step 0 bucket (indices are step-constants)
    int2 bkt = g_bkt[s];            // t = 0
    for (int i = tid; i < bkt.y; i += NTHREADS)
        sb[i] = g_order[bkt.x + i];
    __syncthreads();

    for (int t = 0; t < TN; t++) {
        const __nv_bfloat16* __restrict__ pin = (const __nv_bfloat16*)g_alpha[t & 1];
        __nv_bfloat16* __restrict__ pout = (__nv_bfloat16*)g_alpha[(t & 1) ^ 1];
        const int start = bkt.x, cnt = bkt.y;
        (void)start;

        int o = 0;
        while (o < cnt) {
            const int rem = cnt - o;
            if (rem <= 8) {
                // ========= transposed mode (<=8 rows): D^T = P^T x alpha ====
                const int m = rem;
                if (w < 8) {   // warp w stages alpha row w (zero-padded)
                    uint4 pk = make_uint4(0, 0, 0, 0);
                    if (w < m) {
                        int b = sb[o + w];            // LDS broadcast
                        pk = __ldcg((const uint4*)(pin + b * QN) + lane);
                    }
                    *(uint4*)(sh + A_OFF + w * A_ROW + lane * 16) = pk;
                }
                __syncthreads();

                float d[4] = {0.f, 0.f, 0.f, 0.f};
                float e[4] = {0.f, 0.f, 0.f, 0.f};
                // A-frag = P^T tile: x4.trans on P rows k, cols q'=w*16(+8)
                const unsigned aP = shb + P_OFF
                    + ((lane & 7) + ((lane >> 4) & 1) * 8) * P_ROW
                    + (w * 16 + ((lane >> 3) & 1) * 8) * 2;
                // B-frag = alpha (rows n=m, cols k): NON-trans x2
                const unsigned aAl = shb + A_OFF + (lane & 7) * A_ROW
                    + ((lane >> 3) & 1) * 16;
                #pragma unroll
                for (int k16 = 0; k16 < 16; k16 += 2) {
                    unsigned a[4], b[2];
                    ldmBT(a, aP + k16 * 16 * P_ROW);
                    ldmN2(b, aAl + k16 * 32);
                    mma16816(d, a, b[0], b[1]);
                    unsigned a2[4], b2[2];
                    ldmBT(a2, aP + (k16 + 1) * 16 * P_ROW);
                    ldmN2(b2, aAl + (k16 + 1) * 32);
                    mma16816(e, a2, b2[0], b2[1]);
                }
                #pragma unroll
                for (int r = 0; r < 4; r++) d[r] += e[r];

                // D^T frag: q' = w*16 + lane>>2 (+8), b-slot n = 2*(lane&3)(+1)
                int n = 2 * (lane & 3);
                int qp = w * 16 + (lane >> 2);
                if (n < m) {
                    __nv_bfloat16* r0 = pout + sb[o + n] * QN + qp;
                    r0[0] = __float2bfloat16(d[0] * sc);
                    r0[8] = __float2bfloat16(d[2] * sc);
                }
                if (n + 1 < m) {
                    __nv_bfloat16* r1 = pout + sb[o + n + 1] * QN + qp;
                    r1[0] = __float2bfloat16(d[1] * sc);
                    r1[8] = __float2bfloat16(d[3] * sc);
                }
                __syncthreads();
                o += 8;
            } else if (rem <= MT) {
                // ========= single-tile mode (9..16 rows, 16 warps) ==========
                const int m = rem;
                {   // warp w stages alpha row w (zero-padded)
                    uint4 pk = make_uint4(0, 0, 0, 0);
                    if (w < m) {
                        int b = sb[o + w];
                        pk = __ldcg((const uint4*)(pin + b * QN) + lane);
                    }
                    *(uint4*)(sh + A_OFF + w * A_ROW + lane * 16) = pk;
                }
                __syncthreads();

                float d[2][4], e[2][4];
                #pragma unroll
                for (int j = 0; j < 2; j++)
                    #pragma unroll
                    for (int r = 0; r < 4; r++) { d[j][r] = 0.f; e[j][r] = 0.f; }

                const unsigned aA = shb + A_OFF + (lane & 15) * A_ROW
                                    + (lane >> 4) * 16;
                const unsigned aB = shb + P_OFF + (lane & 15) * P_ROW
                                    + (w * 16 + (lane >> 4) * 8) * 2;
                #pragma unroll
                for (int k16 = 0; k16 < 16; k16 += 2) {
                    unsigned a[4], b[4];
                    ldmA(a, aA + k16 * 32);
                    ldmBT(b, aB + k16 * 16 * P_ROW);
                    mma16816(d[0], a, b[0], b[1]);
                    mma16816(d[1], a, b[2], b[3]);
                    unsigned a2[4], b2[4];
                    ldmA(a2, aA + (k16 + 1) * 32);
                    ldmBT(b2, aB + (k16 + 1) * 16 * P_ROW);
                    mma16816(e[0], a2, b2[0], b2[1]);
                    mma16816(e[1], a2, b2[2], b2[3]);
                }
                #pragma unroll
                for (int j = 0; j < 2; j++)
                    #pragma unroll
                    for (int r = 0; r < 4; r++) d[j][r] += e[j][r];

                unsigned* pu = (unsigned*)pout;
                int m0 = lane >> 2;
                int q0 = w * 16 + 2 * (lane & 3);
                #pragma unroll
                for (int j = 0; j < 2; j++) {
                    int n = q0 + j * 8;
                    if (m0 < m)
                        pu[sb[o + m0] * (QN / 2) + (n >> 1)] =
                            f22bf(d[j][0] * sc, d[j][1] * sc);
                    if (m0 + 8 < m)
                        pu[sb[o + m0 + 8] * (QN / 2) + (n >> 1)] =
                            f22bf(d[j][2] * sc, d[j][3] * sc);
                }
                __syncthreads();
                o += MT;
            } else {
                // ========= two-tile mode (17..32 rows, warp-split) ==========
                const int m = min(rem, 32);
                {   // half-warp per row: row = tid>>4, 32B per thread
                    int row = tid >> 4, seg = tid & 15;
                    uint4 p0 = make_uint4(0,0,0,0), p1 = make_uint4(0,0,0,0);
                    if (row < m) {
                        int b = sb[o + row];
                        const uint4* p = (const uint4*)(pin + b * QN) + seg * 2;
                        p0 = __ldcg(p);
                        p1 = __ldcg(p + 1);
                    }
                    *(uint4*)(sh + A_OFF + row * A_ROW + seg * 32) = p0;
                    *(uint4*)(sh + A_OFF + row * A_ROW + seg * 32 + 16) = p1;
                }
                __syncthreads();

                const int g = w >> 3, wg = w & 7;
                const int mg = min(m - g * MT, MT);
                float d[4][4];
                #pragma unroll
                for (int j = 0; j < 4; j++)
                    #pragma unroll
                    for (int r = 0; r < 4; r++) d[j][r] = 0.0f;

                const unsigned aA = shb + A_OFF + (g * MT + (lane & 15)) * A_ROW
                                    + (lane >> 4) * 16;
                const unsigned aB = shb + P_OFF + (lane & 15) * P_ROW
                                    + (wg * 32 + (lane >> 4) * 8) * 2;
                #pragma unroll
                for (int k16 = 0; k16 < 16; k16++) {
                    unsigned a[4], b[8];
                    ldmA(a, aA + k16 * 32);
                    unsigned baddr = aB + k16 * 16 * P_ROW;
                    ldmBT(b + 0, baddr);
                    ldmBT(b + 4, baddr + 32);
                    mma16816(d[0], a, b[0], b[1]);
                    mma16816(d[1], a, b[2], b[3]);
                    mma16816(d[2], a, b[4], b[5]);
                    mma16816(d[3], a, b[6], b[7]);
                }
                unsigned* pu = (unsigned*)pout;
                int m0 = lane >> 2;
                int q0 = wg * 32 + 2 * (lane & 3);
                #pragma unroll
                for (int j = 0; j < 4; j++) {
                    int n = q0 + j * 8;
                    if (m0 < mg)
                        pu[sb[o + g*MT + m0] * (QN / 2) + (n >> 1)] =
                            f22bf(d[j][0] * sc, d[j][1] * sc);
                    if (m0 + 8 < mg)
                        pu[sb[o + g*MT + m0 + 8] * (QN / 2) + (n >> 1)] =
                            f22bf(d[j][2] * sc, d[j][3] * sc);
                }
                __syncthreads();
                o += 32;
            }
        }

        if (t + 1 < TN) {
            // ---- prefetch step t+1 metadata (step-constants; overlaps skew)
            bkt = g_bkt[(t + 1) * SN + s];
            for (int i = tid; i < bkt.y; i += NTHREADS)
                sb[i] = g_order[(t + 1) * BN + bkt.x + i];

            // ---- grid barrier: release-add, acquire-poll, monotonic target
            if (tid == 0) {
                asm volatile("red.release.gpu.global.add.u32 [%0], 1;"
                             :: "l"(&g_bar) : "memory");
                const unsigned target = (unsigned)(t + 1) * (unsigned)SN;
                unsigned v;
                do {
                    asm volatile("ld.acquire.gpu.u32 %0, [%1];" : "=r"(v) : "l"(&g_bar));
                } while (v < target);
            }
            __syncthreads();   // releases warps; also orders sb prefetch stores
        }
    }
}

// ---------------------------------------------------------------------------
// out[b] = log( sum_q alpha_bf16[b][q] * exp(final[q]) ) + 128*ln(256)
__global__ void final_kernel(const float* __restrict__ finalw, float* __restrict__ out) {
    int b = blockIdx.x * 8 + (threadIdx.x >> 5);
    int lane = threadIdx.x & 31;
    const __nv_bfloat16* ar = (const __nv_bfloat16*)g_alpha[0] + b * QN;  // T even
    float sum = 0.0f;
    #pragma unroll
    for (int i = 0; i < 8; i++) {
        int q = lane + 32 * i;
        sum += __bfloat162float(ar[q]) * __expf(finalw[q]);
    }
    #pragma unroll
    for (int o = 16; o > 0; o >>= 1) sum += __shfl_xor_sync(0xFFFFFFFFu, sum, o);
    if (lane == 0)
        out[b] = logf(sum) + (float)(128.0 * 5.545177444479562);  // T * ln(256)
}

// ---------------------------------------------------------------------------
extern "C" void kernel_launch(void* const* d_in, const int* in_sizes, int n_in,
                              void* d_out, int out_size) {
    const float* A      = (const float*)d_in[0];  // [Q,S,Q] fp32
    const float* init   = (const float*)d_in[1];  // [Q]
    const float* finalw = (const float*)d_in[2];  // [Q]
    const int*   xs     = (const int*)d_in[3];    // [B,T] int32
    float* out = (float*)d_out;                   // [B]

    cudaFuncSetAttribute(fsa_kernel,
                         cudaFuncAttributeMaxDynamicSharedMemorySize, SH_BYTES);

    exp_kernel<<<(SN * QN * QN / 2) / 256, 256>>>(A);
    init_kernel<<<BN, QN>>>(init);
    bucket_kernel<<<TN, 256>>>(xs);
    fsa_kernel<<<SN, NTHREADS, SH_BYTES>>>();
    final_kernel<<<BN / 8, 256>>>(finalw, out);
}

// round 12
// speedup vs baseline: 1.2398x; 1.0902x over previous
#include <cuda_runtime.h>
#include <cuda_bf16.h>

// Problem constants
#define QN 256   // states
#define SN 128   // symbols
#define BN 1024  // batch
#define TN 128   // timesteps
#define NTHREADS 512

// Device scratch (allocation-free rule: static __device__ globals)
__device__ unsigned g_Pbf[SN * QN * QN / 2];     // bf16x2 exp(A), [s][q][q'] : 16 MB
__device__ uint4    g_alpha[2][BN * QN / 8];     // ping-pong bf16 alphas (512B/row)
__device__ int      g_order[TN * BN];            // per-t batch indices grouped by symbol
__device__ int2     g_bkt[TN * SN];              // per (t,s): {start, cnt}
__device__ unsigned g_bar;                       // grid barrier counter (reset per run)

// Dynamic SMEM layout (bytes)
#define A_OFF   0
#define A_ROW   528                       // 512B row + 16B pad: 132 words, 132%32=4
                                          // -> conflict-free LDS.32 B-frag pattern
#define P_OFF   (16 * A_ROW)              // 8448 (P staging, used only at startup)
#define P_ROW   528
#define SB_OFF  (P_OFF + 256 * P_ROW)     // 143616 ; prefetched bucket row list
#define SH_BYTES (SB_OFF + 4096)          // 147712 (dynamic, opt-in; 1 CTA/SM)

// ---------------------------------------------------------------------------
__device__ __forceinline__ unsigned f22bf(float lo, float hi) {
    unsigned r;
    asm("cvt.rn.bf16x2.f32 %0, %1, %2;" : "=r"(r) : "f"(hi), "f"(lo));  // {hi,lo}
    return r;
}
__device__ __forceinline__ void ldmBT(unsigned b[4], unsigned addr) {
    asm volatile("ldmatrix.sync.aligned.m8n8.x4.trans.shared.b16 {%0,%1,%2,%3}, [%4];"
                 : "=r"(b[0]), "=r"(b[1]), "=r"(b[2]), "=r"(b[3]) : "r"(addr));
}
__device__ __forceinline__ void mma16816(float d[4], const unsigned a[4],
                                         unsigned b0, unsigned b1) {
    asm volatile("mma.sync.aligned.m16n8k16.row.col.f32.bf16.bf16.f32 "
                 "{%0,%1,%2,%3},{%4,%5,%6,%7},{%8,%9},{%0,%1,%2,%3};"
                 : "+f"(d[0]), "+f"(d[1]), "+f"(d[2]), "+f"(d[3])
                 : "r"(a[0]), "r"(a[1]), "r"(a[2]), "r"(a[3]), "r"(b0), "r"(b1));
}
__device__ __forceinline__ void cpasync16(unsigned saddr, const void* g) {
    asm volatile("cp.async.cg.shared.global [%0], [%1], 16;" :: "r"(saddr), "l"(g));
}

// ---------------------------------------------------------------------------
// P_bf16[s][q][q'] = bf16(exp(A[q][s][q'])), packed as bf16x2 (q' pairs)
__global__ void exp_kernel(const float* __restrict__ A) {
    int i = blockIdx.x * 256 + threadIdx.x;   // one thread per q'-pair
    int j2 = i & 127;
    int q = (i >> 7) & 255;
    int s = i >> 15;
    float2 v = *(const float2*)(A + (q << 15) + (s << 8) + 2 * j2);
    g_Pbf[(s << 15) + (q << 7) + j2] = f22bf(__expf(v.x), __expf(v.y));
}

// ---------------------------------------------------------------------------
// alpha_0 (bf16, linear space) in buffer 0.
__global__ void init_kernel(const float* __restrict__ init) {
    int b = blockIdx.x;
    int q = threadIdx.x;
    float iv = init[q];
    ((__nv_bfloat16*)g_alpha[0])[b * QN + q] =
        __float2bfloat16((iv > 0.0f) ? iv : 0.0f);
}

// ---------------------------------------------------------------------------
// Per-timestep bucketing; resets the grid barrier counter (stream-ordered).
__global__ void bucket_kernel(const int* __restrict__ xs) {
    int t = blockIdx.x;
    int tid = threadIdx.x;
    if (t == 0 && tid == 0) g_bar = 0u;
    __shared__ int cnt[SN];
    __shared__ int seg[SN];
    __shared__ int off[SN];
    if (tid < SN) cnt[tid] = 0;
    __syncthreads();
    for (int b = tid; b < BN; b += 256)
        atomicAdd(&cnt[xs[b * TN + t]], 1);
    __syncthreads();
    if (tid == 0) {
        int acc = 0;
        for (int s = 0; s < SN; s++) { seg[s] = acc; off[s] = acc; acc += cnt[s]; }
    }
    __syncthreads();
    for (int b = tid; b < BN; b += 256) {
        int s = xs[b * TN + t];
        int pos = atomicAdd(&off[s], 1);
        g_order[t * BN + pos] = b;
    }
    __syncthreads();
    if (tid < SN)
        g_bkt[t * SN + tid] = make_int2(seg[tid], cnt[tid]);
}

// ---------------------------------------------------------------------------
// Persistent FSA kernel: one CTA per symbol. P[s]^T A-fragments are extracted
// ONCE into registers (pa[16][4] per thread = the CTA's full 128 KB slice);
// the step loop never touches P SMEM again. Per step: stage alpha tile
// (zero-padded to 16 rows), then per k16: two conflict-free LDS.32 build the
// B fragment in-place (same element mapping as ldmatrix.x2 non-trans) and one
// register-A MMA accumulates D^T. Groups of 8 batch rows; rows 8-15 reuse pa.
__global__ void __launch_bounds__(NTHREADS, 1) fsa_kernel() {
    extern __shared__ __align__(16) unsigned char sh[];
    unsigned shb = (unsigned)__cvta_generic_to_shared(sh);
    const int s = blockIdx.x;
    const int tid = threadIdx.x, w = tid >> 5, lane = tid & 31;
    int* sb = (int*)(sh + SB_OFF);

    // ---- stage P[s] (256 rows x 512B) into SMEM (startup only)
    {
        const char* gP = (const char*)g_Pbf + ((size_t)s << 17);
        for (int i = tid; i < 256 * 32; i += NTHREADS) {
            int r = i >> 5, c = i & 31;
            cpasync16(shb + P_OFF + r * P_ROW + c * 16, gP + (size_t)r * 512 + c * 16);
        }
        asm volatile("cp.async.commit_group;");
        asm volatile("cp.async.wait_group 0;");
        __syncthreads();
    }

    // ---- extract P^T A-fragments into registers (verified R10 addressing)
    unsigned pa[16][4];
    {
        const unsigned aP = shb + P_OFF
            + ((lane & 7) + ((lane >> 4) & 1) * 8) * P_ROW
            + (w * 16 + ((lane >> 3) & 1) * 8) * 2;
        #pragma unroll
        for (int k16 = 0; k16 < 16; k16++)
            ldmBT(pa[k16], aP + k16 * 16 * P_ROW);
    }

    // ---- prefetch step 0 bucket
    int2 bkt = g_bkt[s];
    for (int i = tid; i < bkt.y; i += NTHREADS)
        sb[i] = g_order[bkt.x + i];
    __syncthreads();

    const float sc = 0.00390625f;   // 2^-8 exact per-step renorm (at epilogue)
    // B-frag LDS base: thread t reads alpha_sm[n = t/4][k = 2(t%4)+{0,1}] (+16B for k+8)
    const unsigned* browB =
        (const unsigned*)(sh + A_OFF + (lane >> 2) * A_ROW) + (lane & 3);
    const int n = 2 * (lane & 3);           // D^T frag batch-col pair
    const int qp = w * 16 + (lane >> 2);    // D^T frag q' row (and +8)

    for (int t = 0; t < TN; t++) {
        const __nv_bfloat16* __restrict__ pin = (const __nv_bfloat16*)g_alpha[t & 1];
        __nv_bfloat16* __restrict__ pout = (__nv_bfloat16*)g_alpha[(t & 1) ^ 1];
        const int cnt = bkt.y;

        int o = 0;
        while (o < cnt) {
            const int mg = min(cnt - o, 16);

            // ---- stage alpha rows o..o+mg-1 (bf16, zero-pad to 16 rows)
            {
                uint4 pk = make_uint4(0, 0, 0, 0);
                if (w < mg)
                    pk = __ldcg((const uint4*)(pin + sb[o + w] * QN) + lane);
                *(uint4*)(sh + A_OFF + w * A_ROW + lane * 16) = pk;
            }
            __syncthreads();

            // ---- group 0 (batch rows o..o+7): dual k-parity chains
            {
                float d[4] = {0.f, 0.f, 0.f, 0.f};
                float e[4] = {0.f, 0.f, 0.f, 0.f};
                #pragma unroll
                for (int k16 = 0; k16 < 16; k16 += 2) {
                    unsigned b0 = browB[k16 * 8];
                    unsigned b1 = browB[k16 * 8 + 4];
                    mma16816(d, pa[k16], b0, b1);
                    unsigned c0 = browB[(k16 + 1) * 8];
                    unsigned c1 = browB[(k16 + 1) * 8 + 4];
                    mma16816(e, pa[k16 + 1], c0, c1);
                }
                #pragma unroll
                for (int r = 0; r < 4; r++) d[r] += e[r];

                if (n < mg) {
                    __nv_bfloat16* r0 = pout + sb[o + n] * QN + qp;
                    r0[0] = __float2bfloat16(d[0] * sc);
                    r0[8] = __float2bfloat16(d[2] * sc);
                }
                if (n + 1 < mg) {
                    __nv_bfloat16* r1 = pout + sb[o + n + 1] * QN + qp;
                    r1[0] = __float2bfloat16(d[1] * sc);
                    r1[8] = __float2bfloat16(d[3] * sc);
                }
            }

            // ---- group 1 (batch rows o+8..o+15), reuses pa registers
            if (mg > 8) {
                const unsigned* browB1 = browB + 8 * (A_ROW / 4);
                float d[4] = {0.f, 0.f, 0.f, 0.f};
                float e[4] = {0.f, 0.f, 0.f, 0.f};
                #pragma unroll
                for (int k16 = 0; k16 < 16; k16 += 2) {
                    unsigned b0 = browB1[k16 * 8];
                    unsigned b1 = browB1[k16 * 8 + 4];
                    mma16816(d, pa[k16], b0, b1);
                    unsigned c0 = browB1[(k16 + 1) * 8];
                    unsigned c1 = browB1[(k16 + 1) * 8 + 4];
                    mma16816(e, pa[k16 + 1], c0, c1);
                }
                #pragma unroll
                for (int r = 0; r < 4; r++) d[r] += e[r];

                if (8 + n < mg) {
                    __nv_bfloat16* r0 = pout + sb[o + 8 + n] * QN + qp;
                    r0[0] = __float2bfloat16(d[0] * sc);
                    r0[8] = __float2bfloat16(d[2] * sc);
                }
                if (9 + n < mg) {
                    __nv_bfloat16* r1 = pout + sb[o + 9 + n] * QN + qp;
                    r1[0] = __float2bfloat16(d[1] * sc);
                    r1[8] = __float2bfloat16(d[3] * sc);
                }
            }
            __syncthreads();   // all warps done with sb + alpha stage
            o += 16;
        }

        if (t + 1 < TN) {
            // ---- prefetch step t+1 metadata (step-constants; overlaps skew)
            bkt = g_bkt[(t + 1) * SN + s];
            for (int i = tid; i < bkt.y; i += NTHREADS)
                sb[i] = g_order[(t + 1) * BN + bkt.x + i];

            // ---- grid barrier: release-add, acquire-poll, monotonic target
            if (tid == 0) {
                asm volatile("red.release.gpu.global.add.u32 [%0], 1;"
                             :: "l"(&g_bar) : "memory");
                const unsigned target = (unsigned)(t + 1) * (unsigned)SN;
                unsigned v;
                do {
                    asm volatile("ld.acquire.gpu.u32 %0, [%1];" : "=r"(v) : "l"(&g_bar));
                } while (v < target);
            }
            __syncthreads();   // releases warps; also orders sb prefetch stores
        }
    }
}

// ---------------------------------------------------------------------------
// out[b] = log( sum_q alpha_bf16[b][q] * exp(final[q]) ) + 128*ln(256)
__global__ void final_kernel(const float* __restrict__ finalw, float* __restrict__ out) {
    int b = blockIdx.x * 8 + (threadIdx.x >> 5);
    int lane = threadIdx.x & 31;
    const __nv_bfloat16* ar = (const __nv_bfloat16*)g_alpha[0] + b * QN;  // T even
    float sum = 0.0f;
    #pragma unroll
    for (int i = 0; i < 8; i++) {
        int q = lane + 32 * i;
        sum += __bfloat162float(ar[q]) * __expf(finalw[q]);
    }
    #pragma unroll
    for (int o = 16; o > 0; o >>= 1) sum += __shfl_xor_sync(0xFFFFFFFFu, sum, o);
    if (lane == 0)
        out[b] = logf(sum) + (float)(128.0 * 5.545177444479562);  // T * ln(256)
}

// ---------------------------------------------------------------------------
extern "C" void kernel_launch(void* const* d_in, const int* in_sizes, int n_in,
                              void* d_out, int out_size) {
    const float* A      = (const float*)d_in[0];  // [Q,S,Q] fp32
    const float* init   = (const float*)d_in[1];  // [Q]
    const float* finalw = (const float*)d_in[2];  // [Q]
    const int*   xs     = (const int*)d_in[3];    // [B,T] int32
    float* out = (float*)d_out;                   // [B]

    cudaFuncSetAttribute(fsa_kernel,
                         cudaFuncAttributeMaxDynamicSharedMemorySize, SH_BYTES);

    exp_kernel<<<(SN * QN * QN / 2) / 256, 256>>>(A);
    init_kernel<<<BN, QN>>>(init);
    bucket_kernel<<<TN, 256>>>(xs);
    fsa_kernel<<<SN, NTHREADS, SH_BYTES>>>();
    final_kernel<<<BN / 8, 256>>>(finalw, out);
}

// round 13
// speedup vs baseline: 1.2736x; 1.0273x over previous
#include <cuda_runtime.h>
#include <cuda_bf16.h>

// Problem constants
#define QN 256   // states
#define SN 128   // symbols
#define BN 1024  // batch
#define TN 128   // timesteps
#define NTHREADS 512

// Device scratch (allocation-free rule: static __device__ globals)
__device__ unsigned g_Pbf[SN * QN * QN / 2];     // bf16x2 exp(A), [s][q][q'] : 16 MB
__device__ uint4    g_alpha[2][BN * QN / 8];     // ping-pong bf16 alphas (512B/row)
__device__ int      g_order[TN * BN];            // per-t batch indices grouped by symbol
__device__ int2     g_bkt[TN * SN];              // per (t,s): {start, cnt}
__device__ unsigned g_bar;                       // grid barrier counter (reset per run)

// Dynamic SMEM layout (bytes)
#define A_ROW   528                       // 512B row + 16B pad (conflict-free LDS.32)
#define A_OFF   0                         // 32 staged alpha rows
#define P_OFF   (32 * A_ROW)              // 16896 (P staging, startup only)
#define P_ROW   528
#define SB_OFF  (P_OFF + 256 * P_ROW)     // 152064 ; double-buffered bucket lists
#define SH_BYTES (SB_OFF + 4096)          // 156160 (dynamic, opt-in; 1 CTA/SM)

// ---------------------------------------------------------------------------
__device__ __forceinline__ unsigned f22bf(float lo, float hi) {
    unsigned r;
    asm("cvt.rn.bf16x2.f32 %0, %1, %2;" : "=r"(r) : "f"(hi), "f"(lo));  // {hi,lo}
    return r;
}
__device__ __forceinline__ void ldmBT(unsigned b[4], unsigned addr) {
    asm volatile("ldmatrix.sync.aligned.m8n8.x4.trans.shared.b16 {%0,%1,%2,%3}, [%4];"
                 : "=r"(b[0]), "=r"(b[1]), "=r"(b[2]), "=r"(b[3]) : "r"(addr));
}
__device__ __forceinline__ void mma16816(float d[4], const unsigned a[4],
                                         unsigned b0, unsigned b1) {
    asm volatile("mma.sync.aligned.m16n8k16.row.col.f32.bf16.bf16.f32 "
                 "{%0,%1,%2,%3},{%4,%5,%6,%7},{%8,%9},{%0,%1,%2,%3};"
                 : "+f"(d[0]), "+f"(d[1]), "+f"(d[2]), "+f"(d[3])
                 : "r"(a[0]), "r"(a[1]), "r"(a[2]), "r"(a[3]), "r"(b0), "r"(b1));
}
__device__ __forceinline__ void cpasync16(unsigned saddr, const void* g) {
    asm volatile("cp.async.cg.shared.global [%0], [%1], 16;" :: "r"(saddr), "l"(g));
}

// ---------------------------------------------------------------------------
// P_bf16[s][q][q'] = bf16(exp(A[q][s][q'])), packed as bf16x2 (q' pairs)
__global__ void exp_kernel(const float* __restrict__ A) {
    int i = blockIdx.x * 256 + threadIdx.x;   // one thread per q'-pair
    int j2 = i & 127;
    int q = (i >> 7) & 255;
    int s = i >> 15;
    float2 v = *(const float2*)(A + (q << 15) + (s << 8) + 2 * j2);
    g_Pbf[(s << 15) + (q << 7) + j2] = f22bf(__expf(v.x), __expf(v.y));
}

// ---------------------------------------------------------------------------
// alpha_0 (bf16, linear space) in buffer 0.
__global__ void init_kernel(const float* __restrict__ init) {
    int b = blockIdx.x;
    int q = threadIdx.x;
    float iv = init[q];
    ((__nv_bfloat16*)g_alpha[0])[b * QN + q] =
        __float2bfloat16((iv > 0.0f) ? iv : 0.0f);
}

// ---------------------------------------------------------------------------
// Per-timestep bucketing; resets the grid barrier counter (stream-ordered).
__global__ void bucket_kernel(const int* __restrict__ xs) {
    int t = blockIdx.x;
    int tid = threadIdx.x;
    if (t == 0 && tid == 0) g_bar = 0u;
    __shared__ int cnt[SN];
    __shared__ int seg[SN];
    __shared__ int off[SN];
    if (tid < SN) cnt[tid] = 0;
    __syncthreads();
    for (int b = tid; b < BN; b += 256)
        atomicAdd(&cnt[xs[b * TN + t]], 1);
    __syncthreads();
    if (tid == 0) {
        int acc = 0;
        for (int s = 0; s < SN; s++) { seg[s] = acc; off[s] = acc; acc += cnt[s]; }
    }
    __syncthreads();
    for (int b = tid; b < BN; b += 256) {
        int s = xs[b * TN + t];
        int pos = atomicAdd(&off[s], 1);
        g_order[t * BN + pos] = b;
    }
    __syncthreads();
    if (tid < SN)
        g_bkt[t * SN + tid] = make_int2(seg[tid], cnt[tid]);
}

// ---------------------------------------------------------------------------
// One 16-row tile: D^T = P^T x alpha (register A-frags), 4 interleaved MMA
// chains (group0 rows 0-7, group1 rows 8-15, each split by k-parity).
// Zero-padded rows make unconditional group1 compute safe; store guards by mg.
__device__ __forceinline__ void compute_tile(
    const unsigned (&pa)[16][4], const unsigned* browB, int mg,
    const int* sbrow, __nv_bfloat16* __restrict__ pout,
    int n, int qp, float sc)
{
    const unsigned* browB1 = browB + 8 * (A_ROW / 4);
    float d0[4] = {0.f, 0.f, 0.f, 0.f}, e0[4] = {0.f, 0.f, 0.f, 0.f};
    float d1[4] = {0.f, 0.f, 0.f, 0.f}, e1[4] = {0.f, 0.f, 0.f, 0.f};
    #pragma unroll
    for (int k16 = 0; k16 < 16; k16 += 2) {
        mma16816(d0, pa[k16],     browB[k16 * 8],        browB[k16 * 8 + 4]);
        mma16816(d1, pa[k16],     browB1[k16 * 8],       browB1[k16 * 8 + 4]);
        mma16816(e0, pa[k16 + 1], browB[(k16 + 1) * 8],  browB[(k16 + 1) * 8 + 4]);
        mma16816(e1, pa[k16 + 1], browB1[(k16 + 1) * 8], browB1[(k16 + 1) * 8 + 4]);
    }
    #pragma unroll
    for (int r = 0; r < 4; r++) { d0[r] += e0[r]; d1[r] += e1[r]; }

    if (n < mg) {
        __nv_bfloat16* r0 = pout + sbrow[n] * QN + qp;
        r0[0] = __float2bfloat16(d0[0] * sc);
        r0[8] = __float2bfloat16(d0[2] * sc);
    }
    if (n + 1 < mg) {
        __nv_bfloat16* r1 = pout + sbrow[n + 1] * QN + qp;
        r1[0] = __float2bfloat16(d0[1] * sc);
        r1[8] = __float2bfloat16(d0[3] * sc);
    }
    if (8 + n < mg) {
        __nv_bfloat16* r0 = pout + sbrow[8 + n] * QN + qp;
        r0[0] = __float2bfloat16(d1[0] * sc);
        r0[8] = __float2bfloat16(d1[2] * sc);
    }
    if (9 + n < mg) {
        __nv_bfloat16* r1 = pout + sbrow[9 + n] * QN + qp;
        r1[0] = __float2bfloat16(d1[1] * sc);
        r1[8] = __float2bfloat16(d1[3] * sc);
    }
}

// ---------------------------------------------------------------------------
// Persistent FSA kernel: one CTA per symbol. P^T A-frags extracted once into
// registers. Per step: stage alpha (up to 32 rows), prefetch t+1 metadata in
// the MMA shadow (double-buffered sb), interleaved 4-chain GEMM, epilogue,
// grid barrier directly after the epilogue sync.
__global__ void __launch_bounds__(NTHREADS, 1) fsa_kernel() {
    extern __shared__ __align__(16) unsigned char sh[];
    unsigned shb = (unsigned)__cvta_generic_to_shared(sh);
    const int s = blockIdx.x;
    const int tid = threadIdx.x, w = tid >> 5, lane = tid & 31;
    int* sbuf0 = (int*)(sh + SB_OFF);
    int* sbuf1 = sbuf0 + 512;

    // ---- stage P[s] (256 rows x 512B) into SMEM (startup only)
    {
        const char* gP = (const char*)g_Pbf + ((size_t)s << 17);
        for (int i = tid; i < 256 * 32; i += NTHREADS) {
            int r = i >> 5, c = i & 31;
            cpasync16(shb + P_OFF + r * P_ROW + c * 16, gP + (size_t)r * 512 + c * 16);
        }
        asm volatile("cp.async.commit_group;");
        asm volatile("cp.async.wait_group 0;");
        __syncthreads();
    }

    // ---- extract P^T A-fragments into registers (verified addressing)
    unsigned pa[16][4];
    {
        const unsigned aP = shb + P_OFF
            + ((lane & 7) + ((lane >> 4) & 1) * 8) * P_ROW
            + (w * 16 + ((lane >> 3) & 1) * 8) * 2;
        #pragma unroll
        for (int k16 = 0; k16 < 16; k16++)
            ldmBT(pa[k16], aP + k16 * 16 * P_ROW);
    }

    // ---- prefetch step 0 bucket into sbuf0
    int2 bkt = g_bkt[s];
    for (int i = tid; i < bkt.y; i += NTHREADS)
        sbuf0[i] = g_order[bkt.x + i];
    __syncthreads();

    const float sc = 0.00390625f;   // 2^-8 exact per-step renorm (at epilogue)
    const unsigned* browB =
        (const unsigned*)(sh + A_OFF + (lane >> 2) * A_ROW) + (lane & 3);
    const int n = 2 * (lane & 3);           // D^T frag batch-col pair
    const int qp = w * 16 + (lane >> 2);    // D^T frag q' row (and +8)

    for (int t = 0; t < TN; t++) {
        const __nv_bfloat16* __restrict__ pin = (const __nv_bfloat16*)g_alpha[t & 1];
        __nv_bfloat16* __restrict__ pout = (__nv_bfloat16*)g_alpha[(t & 1) ^ 1];
        int* sbc = (t & 1) ? sbuf1 : sbuf0;
        int* sbn = (t & 1) ? sbuf0 : sbuf1;
        const int cnt = bkt.y;

        // t+1 bucket bounds: independent LDG, issued before staging
        int2 bktn = make_int2(0, 0);
        if (t + 1 < TN) bktn = g_bkt[(t + 1) * SN + s];

        int o = 0;
        while (o < cnt) {
            const int mg = min(cnt - o, 32);
            const int rmax = (mg <= 16) ? 16 : 32;

            // ---- stage alpha rows (bf16, zero-pad)
            for (int r = w; r < rmax; r += 16) {
                uint4 pk = make_uint4(0, 0, 0, 0);
                if (r < mg)
                    pk = __ldcg((const uint4*)(pin + sbc[o + r] * QN) + lane);
                *(uint4*)(sh + A_OFF + r * A_ROW + lane * 16) = pk;
            }
            __syncthreads();

            // ---- prefetch t+1 row list in the MMA shadow (once per step)
            if (o == 0 && t + 1 < TN)
                for (int i = tid; i < bktn.y; i += NTHREADS)
                    sbn[i] = g_order[(t + 1) * BN + bktn.x + i];

            // ---- tile 0 (rows o..o+15)
            compute_tile(pa, browB, min(mg, 16), sbc + o, pout, n, qp, sc);
            // ---- tile 1 (rows o+16..o+31), rare straggler path
            if (mg > 16)
                compute_tile(pa, browB + 16 * (A_ROW / 4), mg - 16,
                             sbc + o + 16, pout, n, qp, sc);

            __syncthreads();   // epilogue stores + sbn prefetch complete
            o += 32;
        }

        // ---- grid barrier: release-add, acquire-poll, monotonic target
        if (t + 1 < TN) {
            if (tid == 0) {
                asm volatile("red.release.gpu.global.add.u32 [%0], 1;"
                             :: "l"(&g_bar) : "memory");
                const unsigned target = (unsigned)(t + 1) * (unsigned)SN;
                unsigned v;
                do {
                    asm volatile("ld.acquire.gpu.u32 %0, [%1];" : "=r"(v) : "l"(&g_bar));
                } while (v < target);
            }
            __syncthreads();
        }
        bkt = bktn;
    }
}

// ---------------------------------------------------------------------------
// out[b] = log( sum_q alpha_bf16[b][q] * exp(final[q]) ) + 128*ln(256)
__global__ void final_kernel(const float* __restrict__ finalw, float* __restrict__ out) {
    int b = blockIdx.x * 8 + (threadIdx.x >> 5);
    int lane = threadIdx.x & 31;
    const __nv_bfloat16* ar = (const __nv_bfloat16*)g_alpha[0] + b * QN;  // T even
    float sum = 0.0f;
    #pragma unroll
    for (int i = 0; i < 8; i++) {
        int q = lane + 32 * i;
        sum += __bfloat162float(ar[q]) * __expf(finalw[q]);
    }
    #pragma unroll
    for (int o = 16; o > 0; o >>= 1) sum += __shfl_xor_sync(0xFFFFFFFFu, sum, o);
    if (lane == 0)
        out[b] = logf(sum) + (float)(128.0 * 5.545177444479562);  // T * ln(256)
}

// ---------------------------------------------------------------------------
extern "C" void kernel_launch(void* const* d_in, const int* in_sizes, int n_in,
                              void* d_out, int out_size) {
    const float* A      = (const float*)d_in[0];  // [Q,S,Q] fp32
    const float* init   = (const float*)d_in[1];  // [Q]
    const float* finalw = (const float*)d_in[2];  // [Q]
    const int*   xs     = (const int*)d_in[3];    // [B,T] int32
    float* out = (float*)d_out;                   // [B]

    cudaFuncSetAttribute(fsa_kernel,
                         cudaFuncAttributeMaxDynamicSharedMemorySize, SH_BYTES);

    exp_kernel<<<(SN * QN * QN / 2) / 256, 256>>>(A);
    init_kernel<<<BN, QN>>>(init);
    bucket_kernel<<<TN, 256>>>(xs);
    fsa_kernel<<<SN, NTHREADS, SH_BYTES>>>();
    final_kernel<<<BN / 8, 256>>>(finalw, out);
}